// round 1
// baseline (speedup 1.0000x reference)
#include <cuda_runtime.h>
#include <cstdint>

// Problem constants (fixed by the reference)
#define NN   100000      // nodes
#define EE   1600000     // edges
#define NCLI 1000000     // client table rows
#define DD   128         // feature dim (= H)

// ---------------- scratch (static device globals; no allocation) -------------
__device__ float g_X  [(size_t)NN * DD];   // layer input features
__device__ float g_H  [(size_t)NN * DD];   // layer-1 output
__device__ float g_AGG[(size_t)NN * DD];   // neighbor mean
__device__ int   g_deg[NN];
__device__ float g_invdeg[NN];
__device__ int   g_rowptr[NN + 1];
__device__ int   g_pos[NN];
__device__ int   g_esrc[EE];

// ---------------- small helpers ---------------------------------------------
__device__ __forceinline__ unsigned f2tf32(float x) {
    unsigned u;
    asm("cvt.rna.tf32.f32 %0, %1;" : "=r"(u) : "f"(x));
    return u;
}

__device__ __forceinline__ void mma_tf32(float c[4],
                                         unsigned a0, unsigned a1, unsigned a2, unsigned a3,
                                         unsigned b0, unsigned b1) {
    asm volatile(
        "mma.sync.aligned.m16n8k8.row.col.f32.tf32.tf32.f32 "
        "{%0,%1,%2,%3}, {%4,%5,%6,%7}, {%8,%9}, {%0,%1,%2,%3};\n"
        : "+f"(c[0]), "+f"(c[1]), "+f"(c[2]), "+f"(c[3])
        : "r"(a0), "r"(a1), "r"(a2), "r"(a3), "r"(b0), "r"(b1));
}

// ---------------- kernels ----------------------------------------------------

__global__ void k_zero_deg() {
    int i = blockIdx.x * blockDim.x + threadIdx.x;
    if (i < NN) g_deg[i] = 0;
}

// warp per node: gather embedding row (client or item table)
__global__ void k_embed(const float* __restrict__ ctab,
                        const float* __restrict__ itab,
                        const int*   __restrict__ node_ids) {
    int gw   = (blockIdx.x * blockDim.x + threadIdx.x) >> 5;
    int lane = threadIdx.x & 31;
    if (gw >= NN) return;
    int id = node_ids[gw];
    const float* src = (id < NCLI) ? (ctab + (size_t)id * DD)
                                   : (itab + (size_t)(id - NCLI) * DD);
    float4 v = *reinterpret_cast<const float4*>(src + lane * 4);
    *reinterpret_cast<float4*>(g_X + (size_t)gw * DD + lane * 4) = v;
}

__global__ void k_deg(const int* __restrict__ dst) {
    int e = blockIdx.x * blockDim.x + threadIdx.x;
    if (e < EE) atomicAdd(&g_deg[dst[e]], 1);
}

// single-block exclusive scan over degrees -> row_ptr, pos, inv_deg
__global__ void k_scan() {
    __shared__ int wsum[32];
    __shared__ int sh_total;
    __shared__ int sh_carry;
    int tid = threadIdx.x, lane = tid & 31, w = tid >> 5;
    if (tid == 0) sh_carry = 0;
    __syncthreads();
    const int TILES = (NN + 1023) >> 10;
    for (int t = 0; t < TILES; ++t) {
        int i = (t << 10) + tid;
        int v = (i < NN) ? g_deg[i] : 0;
        int inc = v;
        #pragma unroll
        for (int off = 1; off < 32; off <<= 1) {
            int y = __shfl_up_sync(0xffffffffu, inc, off);
            if (lane >= off) inc += y;
        }
        if (lane == 31) wsum[w] = inc;
        __syncthreads();
        if (w == 0) {
            int s = wsum[lane];
            int inc2 = s;
            #pragma unroll
            for (int off = 1; off < 32; off <<= 1) {
                int y = __shfl_up_sync(0xffffffffu, inc2, off);
                if (lane >= off) inc2 += y;
            }
            wsum[lane] = inc2 - s;          // exclusive warp offset
            if (lane == 31) sh_total = inc2;
        }
        __syncthreads();
        int incl = inc + wsum[w];
        int base = sh_carry;
        if (i < NN) {
            int excl = base + incl - v;
            g_rowptr[i] = excl;
            g_pos[i]    = excl;
            g_invdeg[i] = 1.0f / (float)(v > 0 ? v : 1);
        }
        __syncthreads();
        if (tid == 0) sh_carry = base + sh_total;
        __syncthreads();
    }
    if (threadIdx.x == 0) g_rowptr[NN] = sh_carry;
}

__global__ void k_scatter(const int* __restrict__ src, const int* __restrict__ dst) {
    int e = blockIdx.x * blockDim.x + threadIdx.x;
    if (e >= EE) return;
    int d = dst[e];
    int p = atomicAdd(&g_pos[d], 1);
    g_esrc[p] = src[e];
}

// warp per node: mean over in-neighbors (CSR), pure reads — no float atomics
__global__ void k_agg(int sel_x) {
    int gw   = (blockIdx.x * blockDim.x + threadIdx.x) >> 5;
    int lane = threadIdx.x & 31;
    if (gw >= NN) return;
    const float* __restrict__ X = sel_x ? g_H : g_X;
    int s = g_rowptr[gw], e = g_rowptr[gw + 1];
    float4 acc = make_float4(0.f, 0.f, 0.f, 0.f);
    int i = s;
    for (; i + 4 <= e; i += 4) {
        int s0 = g_esrc[i], s1 = g_esrc[i + 1], s2 = g_esrc[i + 2], s3 = g_esrc[i + 3];
        float4 v0 = *reinterpret_cast<const float4*>(X + (size_t)s0 * DD + lane * 4);
        float4 v1 = *reinterpret_cast<const float4*>(X + (size_t)s1 * DD + lane * 4);
        float4 v2 = *reinterpret_cast<const float4*>(X + (size_t)s2 * DD + lane * 4);
        float4 v3 = *reinterpret_cast<const float4*>(X + (size_t)s3 * DD + lane * 4);
        acc.x += v0.x + v1.x + v2.x + v3.x;
        acc.y += v0.y + v1.y + v2.y + v3.y;
        acc.z += v0.z + v1.z + v2.z + v3.z;
        acc.w += v0.w + v1.w + v2.w + v3.w;
    }
    for (; i < e; ++i) {
        int s0 = g_esrc[i];
        float4 v0 = *reinterpret_cast<const float4*>(X + (size_t)s0 * DD + lane * 4);
        acc.x += v0.x; acc.y += v0.y; acc.z += v0.z; acc.w += v0.w;
    }
    float inv = g_invdeg[gw];
    acc.x *= inv; acc.y *= inv; acc.z *= inv; acc.w *= inv;
    *reinterpret_cast<float4*>(g_AGG + (size_t)gw * DD + lane * 4) = acc;
}

// ---------------- fused GEMM: out = A_x @ Wself + AGG @ Wneigh + b (opt relu)
// tf32 mma.sync m16n8k8; weights transposed+converted in smem (stride 132 pad)
#define WT_STRIDE 132
#define GEMM_SMEM (2 * 128 * WT_STRIDE * 4)

__device__ __forceinline__ void accum_panel(const float* __restrict__ A,
                                            const unsigned* __restrict__ Wt,
                                            float (*c)[4], int row0, int gid, int tig) {
    for (int k0 = 0; k0 < 128; k0 += 8) {
        int r0 = row0 + gid, r1 = row0 + gid + 8;
        float f0 = 0.f, f1 = 0.f, f2 = 0.f, f3 = 0.f;
        if (r0 < NN) {
            f0 = __ldg(A + (size_t)r0 * DD + k0 + tig);
            f2 = __ldg(A + (size_t)r0 * DD + k0 + tig + 4);
        }
        if (r1 < NN) {
            f1 = __ldg(A + (size_t)r1 * DD + k0 + tig);
            f3 = __ldg(A + (size_t)r1 * DD + k0 + tig + 4);
        }
        unsigned a0 = f2tf32(f0), a1 = f2tf32(f1), a2 = f2tf32(f2), a3 = f2tf32(f3);
        #pragma unroll
        for (int nt = 0; nt < 16; ++nt) {
            unsigned b0 = Wt[(nt * 8 + gid) * WT_STRIDE + k0 + tig];
            unsigned b1 = Wt[(nt * 8 + gid) * WT_STRIDE + k0 + tig + 4];
            mma_tf32(c[nt], a0, a1, a2, a3, b0, b1);
        }
    }
}

__global__ void __launch_bounds__(512, 1)
k_gemm(const float* __restrict__ Wself, const float* __restrict__ Wneigh,
       const float* __restrict__ bias, float* out_ext, int sel_x, int relu) {
    extern __shared__ unsigned smw[];
    unsigned* wt_self  = smw;
    unsigned* wt_neigh = smw + 128 * WT_STRIDE;

    int tid = threadIdx.x;
    // load + transpose + convert weights: W[k][n] -> Wt[n][k] (tf32)
    for (int idx = tid; idx < 128 * 128; idx += 512) {
        int k = idx >> 7, n = idx & 127;
        wt_self [n * WT_STRIDE + k] = f2tf32(Wself [idx]);
        wt_neigh[n * WT_STRIDE + k] = f2tf32(Wneigh[idx]);
    }
    __syncthreads();

    const float* __restrict__ A   = sel_x ? g_H : g_X;
    float* out = out_ext ? out_ext : g_H;

    int warp = tid >> 5, lane = tid & 31;
    int gid = lane >> 2, tig = lane & 3;
    int row0 = blockIdx.x * 256 + warp * 16;

    float c[16][4];
    #pragma unroll
    for (int nt = 0; nt < 16; ++nt)
        c[nt][0] = c[nt][1] = c[nt][2] = c[nt][3] = 0.f;

    accum_panel(A,     wt_self,  c, row0, gid, tig);
    accum_panel(g_AGG, wt_neigh, c, row0, gid, tig);

    int r0 = row0 + gid, r1 = row0 + gid + 8;
    #pragma unroll
    for (int nt = 0; nt < 16; ++nt) {
        int col = nt * 8 + 2 * tig;
        float bx = __ldg(bias + col), by = __ldg(bias + col + 1);
        float v0 = c[nt][0] + bx, v1 = c[nt][1] + by;
        float v2 = c[nt][2] + bx, v3 = c[nt][3] + by;
        if (relu) {
            v0 = fmaxf(v0, 0.f); v1 = fmaxf(v1, 0.f);
            v2 = fmaxf(v2, 0.f); v3 = fmaxf(v3, 0.f);
        }
        if (r0 < NN)
            *reinterpret_cast<float2*>(out + (size_t)r0 * DD + col) = make_float2(v0, v1);
        if (r1 < NN)
            *reinterpret_cast<float2*>(out + (size_t)r1 * DD + col) = make_float2(v2, v3);
    }
}

// ---------------- launch -----------------------------------------------------
extern "C" void kernel_launch(void* const* d_in, const int* in_sizes, int n_in,
                              void* d_out, int out_size) {
    const float* ctab   = (const float*)d_in[0];
    const float* itab   = (const float*)d_in[1];
    const float* Wself1 = (const float*)d_in[2];
    const float* Wneigh1= (const float*)d_in[3];
    const float* b1     = (const float*)d_in[4];
    const float* Wself2 = (const float*)d_in[5];
    const float* Wneigh2= (const float*)d_in[6];
    const float* b2     = (const float*)d_in[7];
    const int*   nids   = (const int*)d_in[8];
    const int*   src    = (const int*)d_in[9];
    const int*   dst    = (const int*)d_in[10];
    float* out = (float*)d_out;

    cudaFuncSetAttribute(k_gemm, cudaFuncAttributeMaxDynamicSharedMemorySize, GEMM_SMEM);

    const int WARP_BLKS = (NN * 32 + 255) / 256;   // warp-per-node kernels
    const int EDGE_BLKS = (EE + 255) / 256;
    const int GEMM_BLKS = (NN + 255) / 256;

    k_zero_deg<<<(NN + 255) / 256, 256>>>();
    k_embed<<<WARP_BLKS, 256>>>(ctab, itab, nids);
    k_deg<<<EDGE_BLKS, 256>>>(dst);
    k_scan<<<1, 1024>>>();
    k_scatter<<<EDGE_BLKS, 256>>>(src, dst);

    // layer 1
    k_agg<<<WARP_BLKS, 256>>>(0);
    k_gemm<<<GEMM_BLKS, 512, GEMM_SMEM>>>(Wself1, Wneigh1, b1, nullptr, 0, 1);
    // layer 2
    k_agg<<<WARP_BLKS, 256>>>(1);
    k_gemm<<<GEMM_BLKS, 512, GEMM_SMEM>>>(Wself2, Wneigh2, b2, out, 1, 0);
}

// round 3
// speedup vs baseline: 1.2026x; 1.2026x over previous
#include <cuda_runtime.h>
#include <cuda_fp16.h>
#include <cstdint>

// Problem constants (fixed by the reference)
#define NN   100000      // nodes
#define EE   1600000     // edges
#define NCLI 1000000     // client table rows
#define DD   128         // feature dim (= H)
#define NB   98          // scan blocks = ceil(NN/1024)

// ---------------- scratch (static device globals; no allocation) -------------
__device__ float  g_X  [(size_t)NN * DD];   // layer input features (fp32)
__device__ float  g_H  [(size_t)NN * DD];   // layer-1 output (fp32)
__device__ __half g_Xh [(size_t)NN * DD];   // fp16 shadow for neighbor gather
__device__ __half g_Hh [(size_t)NN * DD];
__device__ float  g_AGG[(size_t)NN * DD];   // neighbor mean (fp32)
__device__ int    g_deg[NN];
__device__ float  g_invdeg[NN];
__device__ int    g_rowptr[NN + 1];
__device__ int    g_pos[NN];
__device__ int    g_esrc[EE];
__device__ int    g_bsum[NB];
__device__ int    g_boff[NB];

// ---------------- small helpers ---------------------------------------------
__device__ __forceinline__ unsigned f2tf32(float x) {
    unsigned u;
    asm("cvt.rna.tf32.f32 %0, %1;" : "=r"(u) : "f"(x));
    return u;
}

__device__ __forceinline__ void mma_tf32(float c[4],
                                         unsigned a0, unsigned a1, unsigned a2, unsigned a3,
                                         unsigned b0, unsigned b1) {
    asm volatile(
        "mma.sync.aligned.m16n8k8.row.col.f32.tf32.tf32.f32 "
        "{%0,%1,%2,%3}, {%4,%5,%6,%7}, {%8,%9}, {%0,%1,%2,%3};\n"
        : "+f"(c[0]), "+f"(c[1]), "+f"(c[2]), "+f"(c[3])
        : "r"(a0), "r"(a1), "r"(a2), "r"(a3), "r"(b0), "r"(b1));
}

// ---------------- kernels ----------------------------------------------------

__global__ void k_zero_deg() {
    int i = blockIdx.x * blockDim.x + threadIdx.x;
    if (i < NN) g_deg[i] = 0;
}

// warp per node: gather embedding row (client or item table), write fp32 + fp16
__global__ void k_embed(const float* __restrict__ ctab,
                        const float* __restrict__ itab,
                        const int*   __restrict__ node_ids) {
    int gw   = (blockIdx.x * blockDim.x + threadIdx.x) >> 5;
    int lane = threadIdx.x & 31;
    if (gw >= NN) return;
    int id = node_ids[gw];
    const float* src = (id < NCLI) ? (ctab + (size_t)id * DD)
                                   : (itab + (size_t)(id - NCLI) * DD);
    float4 v = *reinterpret_cast<const float4*>(src + lane * 4);
    *reinterpret_cast<float4*>(g_X + (size_t)gw * DD + lane * 4) = v;
    __half2 p0 = __floats2half2_rn(v.x, v.y);
    __half2 p1 = __floats2half2_rn(v.z, v.w);
    uint2 pk = make_uint2(*(unsigned*)&p0, *(unsigned*)&p1);
    *reinterpret_cast<uint2*>(g_Xh + (size_t)gw * DD + lane * 4) = pk;
}

__global__ void k_deg(const int* __restrict__ dst) {
    int e = blockIdx.x * blockDim.x + threadIdx.x;
    if (e < EE) atomicAdd(&g_deg[dst[e]], 1);
}

// ------- parallel 3-phase exclusive scan over degrees -------
// Phase A: per-block exclusive scan (block-local) + block sums
__global__ void k_scan_part() {
    __shared__ int ws[32];
    int blk = blockIdx.x, tid = threadIdx.x;
    int lane = tid & 31, w = tid >> 5;
    int i = blk * 1024 + tid;
    int v = (i < NN) ? g_deg[i] : 0;
    int inc = v;
    #pragma unroll
    for (int off = 1; off < 32; off <<= 1) {
        int y = __shfl_up_sync(0xffffffffu, inc, off);
        if (lane >= off) inc += y;
    }
    if (lane == 31) ws[w] = inc;
    __syncthreads();
    if (w == 0) {
        int s = ws[lane];
        int inc2 = s;
        #pragma unroll
        for (int off = 1; off < 32; off <<= 1) {
            int y = __shfl_up_sync(0xffffffffu, inc2, off);
            if (lane >= off) inc2 += y;
        }
        ws[lane] = inc2 - s;                 // exclusive warp offset
        if (lane == 31) g_bsum[blk] = inc2;  // block total
    }
    __syncthreads();
    if (i < NN) g_rowptr[i] = inc - v + ws[w];   // block-local exclusive
}

// Phase B: scan the NB block sums (1 small block)
__global__ void k_scan_bsum() {
    __shared__ int ws[4];
    int tid = threadIdx.x, lane = tid & 31, w = tid >> 5;
    int v = (tid < NB) ? g_bsum[tid] : 0;
    int inc = v;
    #pragma unroll
    for (int off = 1; off < 32; off <<= 1) {
        int y = __shfl_up_sync(0xffffffffu, inc, off);
        if (lane >= off) inc += y;
    }
    if (lane == 31) ws[w] = inc;
    __syncthreads();
    if (tid == 0) {
        int s = 0;
        #pragma unroll
        for (int j = 0; j < 4; ++j) { int t = ws[j]; ws[j] = s; s += t; }
    }
    __syncthreads();
    int excl = inc - v + ws[w];
    if (tid < NB) g_boff[tid] = excl;
    if (tid == NB - 1) g_rowptr[NN] = excl + v;
}

// Phase C: add block offsets; produce pos, invdeg
__global__ void k_scan_fin() {
    int blk = blockIdx.x;
    int i = blk * 1024 + threadIdx.x;
    if (i >= NN) return;
    int rp = g_rowptr[i] + g_boff[blk];
    g_rowptr[i] = rp;
    g_pos[i]    = rp;
    int d = g_deg[i];
    g_invdeg[i] = 1.0f / (float)(d > 0 ? d : 1);
}

__global__ void k_scatter(const int* __restrict__ src, const int* __restrict__ dst) {
    int e = blockIdx.x * blockDim.x + threadIdx.x;
    if (e >= EE) return;
    int d = dst[e];
    int p = atomicAdd(&g_pos[d], 1);
    g_esrc[p] = src[e];
}

// warp per node: mean over in-neighbors (CSR), fp16 rows, fp32 accumulate
__global__ void k_agg(int sel_x) {
    int gw   = (blockIdx.x * blockDim.x + threadIdx.x) >> 5;
    int lane = threadIdx.x & 31;
    if (gw >= NN) return;
    const __half* __restrict__ X = sel_x ? g_Hh : g_Xh;
    int s = g_rowptr[gw], e = g_rowptr[gw + 1];
    float4 acc = make_float4(0.f, 0.f, 0.f, 0.f);
    const size_t coff = (size_t)lane * 4;
    int i = s;
    for (; i + 4 <= e; i += 4) {
        int s0 = g_esrc[i], s1 = g_esrc[i + 1], s2 = g_esrc[i + 2], s3 = g_esrc[i + 3];
        uint2 u0 = *reinterpret_cast<const uint2*>(X + (size_t)s0 * DD + coff);
        uint2 u1 = *reinterpret_cast<const uint2*>(X + (size_t)s1 * DD + coff);
        uint2 u2 = *reinterpret_cast<const uint2*>(X + (size_t)s2 * DD + coff);
        uint2 u3 = *reinterpret_cast<const uint2*>(X + (size_t)s3 * DD + coff);
        #define ACC(u) { \
            float2 fa = __half22float2(*reinterpret_cast<const __half2*>(&(u).x)); \
            float2 fb = __half22float2(*reinterpret_cast<const __half2*>(&(u).y)); \
            acc.x += fa.x; acc.y += fa.y; acc.z += fb.x; acc.w += fb.y; }
        ACC(u0) ACC(u1) ACC(u2) ACC(u3)
    }
    for (; i < e; ++i) {
        int s0 = g_esrc[i];
        uint2 u0 = *reinterpret_cast<const uint2*>(X + (size_t)s0 * DD + coff);
        ACC(u0)
        #undef ACC
    }
    float inv = g_invdeg[gw];
    acc.x *= inv; acc.y *= inv; acc.z *= inv; acc.w *= inv;
    *reinterpret_cast<float4*>(g_AGG + (size_t)gw * DD + coff) = acc;
}

// ---------------- fused GEMM: out = A_x @ Wself + AGG @ Wneigh + b (opt relu)
// tf32 mma.sync m16n8k8; weights transposed+converted in smem.
// k-within-8 permuted so each thread's (k, k+4) B pair is one LDS.64;
// stride 136 keeps the 16-lane phases on 16 distinct even bank pairs.
#define WT_STRIDE 136
#define GEMM_SMEM (2 * 128 * WT_STRIDE * 4)

__device__ __forceinline__ void accum_panel(const float* __restrict__ A,
                                            const unsigned* __restrict__ Wt,
                                            float (*c)[4], int row0, int gid, int tig) {
    for (int k0 = 0; k0 < 128; k0 += 8) {
        int r0 = row0 + gid, r1 = row0 + gid + 8;
        float f0 = 0.f, f1 = 0.f, f2 = 0.f, f3 = 0.f;
        if (r0 < NN) {
            f0 = __ldg(A + (size_t)r0 * DD + k0 + tig);
            f2 = __ldg(A + (size_t)r0 * DD + k0 + tig + 4);
        }
        if (r1 < NN) {
            f1 = __ldg(A + (size_t)r1 * DD + k0 + tig);
            f3 = __ldg(A + (size_t)r1 * DD + k0 + tig + 4);
        }
        unsigned a0 = f2tf32(f0), a1 = f2tf32(f1), a2 = f2tf32(f2), a3 = f2tf32(f3);
        #pragma unroll
        for (int nt = 0; nt < 16; ++nt) {
            uint2 b = *reinterpret_cast<const uint2*>(
                Wt + (nt * 8 + gid) * WT_STRIDE + k0 + (tig << 1));
            mma_tf32(c[nt], a0, a1, a2, a3, b.x, b.y);
        }
    }
}

__global__ void __launch_bounds__(512, 1)
k_gemm(const float* __restrict__ Wself, const float* __restrict__ Wneigh,
       const float* __restrict__ bias, float* out_ext, int sel_x, int relu) {
    extern __shared__ unsigned smw[];
    unsigned* wt_self  = smw;
    unsigned* wt_neigh = smw + 128 * WT_STRIDE;

    int tid = threadIdx.x;
    // load + transpose + convert weights: W[k][n] -> Wt[n][perm(k)] (tf32)
    for (int idx = tid; idx < 128 * 128; idx += 512) {
        int k = idx >> 7, n = idx & 127;
        int k0 = k & ~7, kk = k & 7;
        int pos = ((kk & 3) << 1) | (kk >> 2);
        wt_self [n * WT_STRIDE + k0 + pos] = f2tf32(Wself [idx]);
        wt_neigh[n * WT_STRIDE + k0 + pos] = f2tf32(Wneigh[idx]);
    }
    __syncthreads();

    const float* __restrict__ A = sel_x ? g_H : g_X;
    float* out = out_ext ? out_ext : g_H;

    int warp = tid >> 5, lane = tid & 31;
    int gid = lane >> 2, tig = lane & 3;
    int row0 = blockIdx.x * 256 + warp * 16;

    float c[16][4];
    #pragma unroll
    for (int nt = 0; nt < 16; ++nt)
        c[nt][0] = c[nt][1] = c[nt][2] = c[nt][3] = 0.f;

    accum_panel(A,     wt_self,  c, row0, gid, tig);
    accum_panel(g_AGG, wt_neigh, c, row0, gid, tig);

    int r0 = row0 + gid, r1 = row0 + gid + 8;
    #pragma unroll
    for (int nt = 0; nt < 16; ++nt) {
        int col = nt * 8 + 2 * tig;
        float bx = __ldg(bias + col), by = __ldg(bias + col + 1);
        float v0 = c[nt][0] + bx, v1 = c[nt][1] + by;
        float v2 = c[nt][2] + bx, v3 = c[nt][3] + by;
        if (relu) {
            v0 = fmaxf(v0, 0.f); v1 = fmaxf(v1, 0.f);
            v2 = fmaxf(v2, 0.f); v3 = fmaxf(v3, 0.f);
        }
        if (r0 < NN) {
            *reinterpret_cast<float2*>(out + (size_t)r0 * DD + col) = make_float2(v0, v1);
            if (relu) {   // layer-1: also write fp16 shadow for next agg
                __half2 p = __floats2half2_rn(v0, v1);
                *reinterpret_cast<unsigned*>(g_Hh + (size_t)r0 * DD + col) = *(unsigned*)&p;
            }
        }
        if (r1 < NN) {
            *reinterpret_cast<float2*>(out + (size_t)r1 * DD + col) = make_float2(v2, v3);
            if (relu) {
                __half2 p = __floats2half2_rn(v2, v3);
                *reinterpret_cast<unsigned*>(g_Hh + (size_t)r1 * DD + col) = *(unsigned*)&p;
            }
        }
    }
}

// ---------------- launch -----------------------------------------------------
extern "C" void kernel_launch(void* const* d_in, const int* in_sizes, int n_in,
                              void* d_out, int out_size) {
    const float* ctab   = (const float*)d_in[0];
    const float* itab   = (const float*)d_in[1];
    const float* Wself1 = (const float*)d_in[2];
    const float* Wneigh1= (const float*)d_in[3];
    const float* b1     = (const float*)d_in[4];
    const float* Wself2 = (const float*)d_in[5];
    const float* Wneigh2= (const float*)d_in[6];
    const float* b2     = (const float*)d_in[7];
    const int*   nids   = (const int*)d_in[8];
    const int*   src    = (const int*)d_in[9];
    const int*   dst    = (const int*)d_in[10];
    float* out = (float*)d_out;

    cudaFuncSetAttribute(k_gemm, cudaFuncAttributeMaxDynamicSharedMemorySize, GEMM_SMEM);

    const int WARP_BLKS = (NN * 32 + 255) / 256;   // warp-per-node kernels
    const int EDGE_BLKS = (EE + 255) / 256;
    const int GEMM_BLKS = (NN + 255) / 256;

    k_zero_deg<<<(NN + 255) / 256, 256>>>();
    k_embed<<<WARP_BLKS, 256>>>(ctab, itab, nids);
    k_deg<<<EDGE_BLKS, 256>>>(dst);
    k_scan_part<<<NB, 1024>>>();
    k_scan_bsum<<<1, 128>>>();
    k_scan_fin<<<NB, 1024>>>();
    k_scatter<<<EDGE_BLKS, 256>>>(src, dst);

    // layer 1
    k_agg<<<WARP_BLKS, 256>>>(0);
    k_gemm<<<GEMM_BLKS, 512, GEMM_SMEM>>>(Wself1, Wneigh1, b1, nullptr, 0, 1);
    // layer 2
    k_agg<<<WARP_BLKS, 256>>>(1);
    k_gemm<<<GEMM_BLKS, 512, GEMM_SMEM>>>(Wself2, Wneigh2, b2, out, 1, 0);
}

// round 4
// speedup vs baseline: 1.5423x; 1.2824x over previous
#include <cuda_runtime.h>
#include <cuda_fp16.h>
#include <cstdint>

// Problem constants (fixed by the reference)
#define NN   100000      // nodes
#define EE   1600000     // edges
#define NCLI 1000000     // client table rows
#define DD   128         // feature dim (= H)
#define NB   98          // scan blocks = ceil(NN/1024)

// ---------------- scratch (static device globals; no allocation) -------------
__device__ __half g_Xh  [(size_t)NN * DD];  // layer-1 input (fp16)
__device__ __half g_Hh  [(size_t)NN * DD];  // layer-1 output (fp16)
__device__ __half g_AGGh[(size_t)NN * DD];  // neighbor mean (fp16)
__device__ int    g_deg[NN];
__device__ float  g_invdeg[NN];
__device__ int    g_rowptr[NN + 1];
__device__ int    g_pos[NN];
__device__ int    g_esrc[EE];
__device__ int    g_bsum[NB];
__device__ int    g_boff[NB];

// ---------------- helpers ----------------------------------------------------
__device__ __forceinline__ void mma_f16(float c[4],
                                        unsigned a0, unsigned a1, unsigned a2, unsigned a3,
                                        unsigned b0, unsigned b1) {
    asm volatile(
        "mma.sync.aligned.m16n8k16.row.col.f32.f16.f16.f32 "
        "{%0,%1,%2,%3}, {%4,%5,%6,%7}, {%8,%9}, {%0,%1,%2,%3};\n"
        : "+f"(c[0]), "+f"(c[1]), "+f"(c[2]), "+f"(c[3])
        : "r"(a0), "r"(a1), "r"(a2), "r"(a3), "r"(b0), "r"(b1));
}

// ---------------- kernels ----------------------------------------------------

__global__ void k_zero_deg() {
    int i = blockIdx.x * blockDim.x + threadIdx.x;
    if (i < NN) g_deg[i] = 0;
}

// warp per node: gather embedding row, convert to fp16
__global__ void k_embed(const float* __restrict__ ctab,
                        const float* __restrict__ itab,
                        const int*   __restrict__ node_ids) {
    int gw   = (blockIdx.x * blockDim.x + threadIdx.x) >> 5;
    int lane = threadIdx.x & 31;
    if (gw >= NN) return;
    int id = node_ids[gw];
    const float* src = (id < NCLI) ? (ctab + (size_t)id * DD)
                                   : (itab + (size_t)(id - NCLI) * DD);
    float4 v = *reinterpret_cast<const float4*>(src + lane * 4);
    __half2 p0 = __floats2half2_rn(v.x, v.y);
    __half2 p1 = __floats2half2_rn(v.z, v.w);
    uint2 pk = make_uint2(*(unsigned*)&p0, *(unsigned*)&p1);
    *reinterpret_cast<uint2*>(g_Xh + (size_t)gw * DD + lane * 4) = pk;
}

__global__ void k_deg(const int* __restrict__ dst) {
    int e = blockIdx.x * blockDim.x + threadIdx.x;
    if (e < EE) atomicAdd(&g_deg[dst[e]], 1);
}

// ------- parallel 3-phase exclusive scan over degrees -------
__global__ void k_scan_part() {
    __shared__ int ws[32];
    int blk = blockIdx.x, tid = threadIdx.x;
    int lane = tid & 31, w = tid >> 5;
    int i = blk * 1024 + tid;
    int v = (i < NN) ? g_deg[i] : 0;
    int inc = v;
    #pragma unroll
    for (int off = 1; off < 32; off <<= 1) {
        int y = __shfl_up_sync(0xffffffffu, inc, off);
        if (lane >= off) inc += y;
    }
    if (lane == 31) ws[w] = inc;
    __syncthreads();
    if (w == 0) {
        int s = ws[lane];
        int inc2 = s;
        #pragma unroll
        for (int off = 1; off < 32; off <<= 1) {
            int y = __shfl_up_sync(0xffffffffu, inc2, off);
            if (lane >= off) inc2 += y;
        }
        ws[lane] = inc2 - s;
        if (lane == 31) g_bsum[blk] = inc2;
    }
    __syncthreads();
    if (i < NN) g_rowptr[i] = inc - v + ws[w];
}

__global__ void k_scan_bsum() {
    __shared__ int ws[4];
    int tid = threadIdx.x, lane = tid & 31, w = tid >> 5;
    int v = (tid < NB) ? g_bsum[tid] : 0;
    int inc = v;
    #pragma unroll
    for (int off = 1; off < 32; off <<= 1) {
        int y = __shfl_up_sync(0xffffffffu, inc, off);
        if (lane >= off) inc += y;
    }
    if (lane == 31) ws[w] = inc;
    __syncthreads();
    if (tid == 0) {
        int s = 0;
        #pragma unroll
        for (int j = 0; j < 4; ++j) { int t = ws[j]; ws[j] = s; s += t; }
    }
    __syncthreads();
    int excl = inc - v + ws[w];
    if (tid < NB) g_boff[tid] = excl;
    if (tid == NB - 1) g_rowptr[NN] = excl + v;
}

__global__ void k_scan_fin() {
    int blk = blockIdx.x;
    int i = blk * 1024 + threadIdx.x;
    if (i >= NN) return;
    int rp = g_rowptr[i] + g_boff[blk];
    g_rowptr[i] = rp;
    g_pos[i]    = rp;
    int d = g_deg[i];
    g_invdeg[i] = 1.0f / (float)(d > 0 ? d : 1);
}

__global__ void k_scatter(const int* __restrict__ src, const int* __restrict__ dst) {
    int e = blockIdx.x * blockDim.x + threadIdx.x;
    if (e >= EE) return;
    int d = dst[e];
    int p = atomicAdd(&g_pos[d], 1);
    g_esrc[p] = src[e];
}

// warp per node: mean over in-neighbors (CSR), fp16 rows, fp32 accumulate,
// fp16 output
__global__ void k_agg(int sel_x) {
    int gw   = (blockIdx.x * blockDim.x + threadIdx.x) >> 5;
    int lane = threadIdx.x & 31;
    if (gw >= NN) return;
    const __half* __restrict__ X = sel_x ? g_Hh : g_Xh;
    int s = g_rowptr[gw], e = g_rowptr[gw + 1];
    float4 acc = make_float4(0.f, 0.f, 0.f, 0.f);
    const size_t coff = (size_t)lane * 4;
    int i = s;
    for (; i + 4 <= e; i += 4) {
        int s0 = g_esrc[i], s1 = g_esrc[i + 1], s2 = g_esrc[i + 2], s3 = g_esrc[i + 3];
        uint2 u0 = *reinterpret_cast<const uint2*>(X + (size_t)s0 * DD + coff);
        uint2 u1 = *reinterpret_cast<const uint2*>(X + (size_t)s1 * DD + coff);
        uint2 u2 = *reinterpret_cast<const uint2*>(X + (size_t)s2 * DD + coff);
        uint2 u3 = *reinterpret_cast<const uint2*>(X + (size_t)s3 * DD + coff);
        #define ACC(u) { \
            float2 fa = __half22float2(*reinterpret_cast<const __half2*>(&(u).x)); \
            float2 fb = __half22float2(*reinterpret_cast<const __half2*>(&(u).y)); \
            acc.x += fa.x; acc.y += fa.y; acc.z += fb.x; acc.w += fb.y; }
        ACC(u0) ACC(u1) ACC(u2) ACC(u3)
    }
    for (; i < e; ++i) {
        int s0 = g_esrc[i];
        uint2 u0 = *reinterpret_cast<const uint2*>(X + (size_t)s0 * DD + coff);
        ACC(u0)
        #undef ACC
    }
    float inv = g_invdeg[gw];
    __half2 o0 = __floats2half2_rn(acc.x * inv, acc.y * inv);
    __half2 o1 = __floats2half2_rn(acc.z * inv, acc.w * inv);
    uint2 pk = make_uint2(*(unsigned*)&o0, *(unsigned*)&o1);
    *reinterpret_cast<uint2*>(g_AGGh + (size_t)gw * DD + coff) = pk;
}

// ---------------- fused GEMM: out = A @ Wself + AGG @ Wneigh + b (opt relu)
// fp16 mma.sync m16n8k16, fp32 accumulate. Weights transposed to [n][k] halves
// in smem, k-within-16 permuted so each thread's (b0,b1) is one LDS.64.
// Row stride 144 halves (288B ≡ 32 mod 128) -> conflict-free 16-lane phases.
#define WT_STRIDE 144                         // halves per n-row
#define GEMM_SMEM (2 * 128 * WT_STRIDE * 2)   // bytes

__device__ __forceinline__ void accum_panel(const __half* __restrict__ A,
                                            const __half* __restrict__ Wt,
                                            float (*c)[4], int row0, int gid, int tig) {
    int r0 = row0 + gid, r1 = row0 + gid + 8;
    bool v0 = r0 < NN, v1 = r1 < NN;
    const __half* a0p = A + (size_t)(v0 ? r0 : 0) * DD;
    const __half* a1p = A + (size_t)(v1 ? r1 : 0) * DD;
    #pragma unroll
    for (int k0 = 0; k0 < 128; k0 += 16) {
        unsigned a0 = v0 ? *(const unsigned*)(a0p + k0 + 2 * tig)     : 0u;
        unsigned a2 = v0 ? *(const unsigned*)(a0p + k0 + 2 * tig + 8) : 0u;
        unsigned a1 = v1 ? *(const unsigned*)(a1p + k0 + 2 * tig)     : 0u;
        unsigned a3 = v1 ? *(const unsigned*)(a1p + k0 + 2 * tig + 8) : 0u;
        #pragma unroll
        for (int nt = 0; nt < 16; ++nt) {
            uint2 b = *reinterpret_cast<const uint2*>(
                Wt + (nt * 8 + gid) * WT_STRIDE + k0 + (tig << 2));
            mma_f16(c[nt], a0, a1, a2, a3, b.x, b.y);
        }
    }
}

__global__ void __launch_bounds__(512, 1)
k_gemm(const float* __restrict__ Wself, const float* __restrict__ Wneigh,
       const float* __restrict__ bias, float* out_ext, int sel_x, int relu) {
    extern __shared__ __half smw[];
    __half* wt_self  = smw;
    __half* wt_neigh = smw + 128 * WT_STRIDE;

    int tid = threadIdx.x;
    // load + transpose + convert: W[k][n] -> Wt[n][perm(k)] (fp16)
    for (int idx = tid; idx < 128 * 128; idx += 512) {
        int k = idx >> 7, n = idx & 127;
        int k0 = k & ~15, kk = k & 15;
        int pos = (((kk & 7) >> 1) << 2) | ((kk >> 3) << 1) | (kk & 1);
        wt_self [n * WT_STRIDE + k0 + pos] = __float2half_rn(Wself [idx]);
        wt_neigh[n * WT_STRIDE + k0 + pos] = __float2half_rn(Wneigh[idx]);
    }
    __syncthreads();

    const __half* __restrict__ A = sel_x ? g_Hh : g_Xh;

    int warp = tid >> 5, lane = tid & 31;
    int gid = lane >> 2, tig = lane & 3;
    int row0 = blockIdx.x * 256 + warp * 16;

    float c[16][4];
    #pragma unroll
    for (int nt = 0; nt < 16; ++nt)
        c[nt][0] = c[nt][1] = c[nt][2] = c[nt][3] = 0.f;

    accum_panel(A,      wt_self,  c, row0, gid, tig);
    accum_panel(g_AGGh, wt_neigh, c, row0, gid, tig);

    int r0 = row0 + gid, r1 = row0 + gid + 8;
    #pragma unroll
    for (int nt = 0; nt < 16; ++nt) {
        int col = nt * 8 + 2 * tig;
        float bx = __ldg(bias + col), by = __ldg(bias + col + 1);
        float v0 = c[nt][0] + bx, v1 = c[nt][1] + by;
        float v2 = c[nt][2] + bx, v3 = c[nt][3] + by;
        if (relu) {   // layer 1: relu, fp16 shadow only
            v0 = fmaxf(v0, 0.f); v1 = fmaxf(v1, 0.f);
            v2 = fmaxf(v2, 0.f); v3 = fmaxf(v3, 0.f);
            if (r0 < NN) {
                __half2 p = __floats2half2_rn(v0, v1);
                *reinterpret_cast<unsigned*>(g_Hh + (size_t)r0 * DD + col) = *(unsigned*)&p;
            }
            if (r1 < NN) {
                __half2 p = __floats2half2_rn(v2, v3);
                *reinterpret_cast<unsigned*>(g_Hh + (size_t)r1 * DD + col) = *(unsigned*)&p;
            }
        } else {      // layer 2: fp32 final output
            if (r0 < NN)
                *reinterpret_cast<float2*>(out_ext + (size_t)r0 * DD + col) = make_float2(v0, v1);
            if (r1 < NN)
                *reinterpret_cast<float2*>(out_ext + (size_t)r1 * DD + col) = make_float2(v2, v3);
        }
    }
}

// ---------------- launch -----------------------------------------------------
extern "C" void kernel_launch(void* const* d_in, const int* in_sizes, int n_in,
                              void* d_out, int out_size) {
    const float* ctab   = (const float*)d_in[0];
    const float* itab   = (const float*)d_in[1];
    const float* Wself1 = (const float*)d_in[2];
    const float* Wneigh1= (const float*)d_in[3];
    const float* b1     = (const float*)d_in[4];
    const float* Wself2 = (const float*)d_in[5];
    const float* Wneigh2= (const float*)d_in[6];
    const float* b2     = (const float*)d_in[7];
    const int*   nids   = (const int*)d_in[8];
    const int*   src    = (const int*)d_in[9];
    const int*   dst    = (const int*)d_in[10];
    float* out = (float*)d_out;

    cudaFuncSetAttribute(k_gemm, cudaFuncAttributeMaxDynamicSharedMemorySize, GEMM_SMEM);

    const int WARP_BLKS = (NN * 32 + 255) / 256;
    const int EDGE_BLKS = (EE + 255) / 256;
    const int GEMM_BLKS = (NN + 255) / 256;

    k_zero_deg<<<(NN + 255) / 256, 256>>>();
    k_embed<<<WARP_BLKS, 256>>>(ctab, itab, nids);
    k_deg<<<EDGE_BLKS, 256>>>(dst);
    k_scan_part<<<NB, 1024>>>();
    k_scan_bsum<<<1, 128>>>();
    k_scan_fin<<<NB, 1024>>>();
    k_scatter<<<EDGE_BLKS, 256>>>(src, dst);

    // layer 1
    k_agg<<<WARP_BLKS, 256>>>(0);
    k_gemm<<<GEMM_BLKS, 512, GEMM_SMEM>>>(Wself1, Wneigh1, b1, nullptr, 0, 1);
    // layer 2
    k_agg<<<WARP_BLKS, 256>>>(1);
    k_gemm<<<GEMM_BLKS, 512, GEMM_SMEM>>>(Wself2, Wneigh2, b2, out, 1, 0);
}